// round 3
// baseline (speedup 1.0000x reference)
#include <cuda_runtime.h>

// LessonGCN on GB300: out = GCNConv(relu(GCNConv(x)))
// Reordering trick: A_norm @ (x @ W1) == (A_norm @ x) @ W1  -> aggregate at 64 dims.
// Layer 2 (OUT_DIM=1) fused into GEMM epilogue: h2 = relu(y@W1+b1) @ W2.
// NOTE: edge_index is int32 (JAX x64-disabled downcasts the requested int64).

#define N_NODES 100000
#define N_EDGES 1600000
#define IN_DIM  64
#define HID_DIM 128

__device__ float g_deg[N_NODES];
__device__ float g_dinv[N_NODES];
__device__ __align__(16) float g_y[(size_t)N_NODES * IN_DIM];
__device__ float g_h2[N_NODES];

__global__ void k_zero_deg() {
    int i = blockIdx.x * blockDim.x + threadIdx.x;
    if (i < N_NODES) g_deg[i] = 0.0f;
}

__global__ void k_deg(const int* __restrict__ dst) {
    int e = blockIdx.x * blockDim.x + threadIdx.x;
    if (e >= N_EDGES) return;
    unsigned d = (unsigned)dst[e];
    if (d < N_NODES) atomicAdd(&g_deg[d], 1.0f);
}

// i indexes (node, float4-chunk): i = n*16 + c, which is exactly x viewed as float4[].
__global__ void k_dinv_init(const float4* __restrict__ x) {
    int i = blockIdx.x * blockDim.x + threadIdx.x;
    if (i >= N_NODES * (IN_DIM / 4)) return;
    int n = i >> 4;
    int c = i & 15;
    float dinv = rsqrtf(g_deg[n] + 1.0f);
    if (c == 0) g_dinv[n] = dinv;
    float s = dinv * dinv;
    float4 v = x[i];
    v.x *= s; v.y *= s; v.z *= s; v.w *= s;
    reinterpret_cast<float4*>(g_y)[i] = v;
}

// One thread per (edge, float4-chunk): 16 consecutive threads cover one edge's 64 floats.
// Gather x[src] coalesced (float4), scatter-add into y[dst] with 4 scalar REDs.
__global__ void k_agg_x(const float4* __restrict__ x,
                        const int* __restrict__ src,
                        const int* __restrict__ dst) {
    int t = blockIdx.x * blockDim.x + threadIdx.x;
    int e = t >> 4;
    int c = t & 15;
    if (e >= N_EDGES) return;
    unsigned s = (unsigned)src[e];
    unsigned d = (unsigned)dst[e];
    if (s >= N_NODES || d >= N_NODES) return;  // never taken with valid data
    float norm = g_dinv[s] * g_dinv[d];
    float4 v = x[s * 16 + c];
    float* p = g_y + ((size_t)d * IN_DIM + c * 4);
    atomicAdd(p + 0, v.x * norm);
    atomicAdd(p + 1, v.y * norm);
    atomicAdd(p + 2, v.z * norm);
    atomicAdd(p + 3, v.w * norm);
}

// Fused GEMM: h2[n] = relu(y_n @ W1 + b1) . W2 ; out[n] = h2[n]*dinv^2 + b2[0]
// W1 (32KB) + b1 + W2 staged in smem; all lanes read the same W element -> broadcast LDS.
__global__ __launch_bounds__(256) void k_gemm_fused(
    const float* __restrict__ W1, const float* __restrict__ b1,
    const float* __restrict__ W2, const float* __restrict__ b2,
    float* __restrict__ out) {
    __shared__ __align__(16) float sW1[IN_DIM * HID_DIM];
    __shared__ __align__(16) float sB1[HID_DIM];
    __shared__ __align__(16) float sW2[HID_DIM];

    for (int i = threadIdx.x; i < IN_DIM * HID_DIM; i += 256) sW1[i] = W1[i];
    if (threadIdx.x < HID_DIM) {
        sB1[threadIdx.x] = b1[threadIdx.x];
        sW2[threadIdx.x] = W2[threadIdx.x];
    }
    __syncthreads();

    int n = blockIdx.x * 256 + threadIdx.x;
    if (n >= N_NODES) return;

    float yr[IN_DIM];
    const float4* yp = reinterpret_cast<const float4*>(g_y + (size_t)n * IN_DIM);
#pragma unroll
    for (int k4 = 0; k4 < IN_DIM / 4; k4++) {
        float4 v = yp[k4];
        yr[4 * k4 + 0] = v.x;
        yr[4 * k4 + 1] = v.y;
        yr[4 * k4 + 2] = v.z;
        yr[4 * k4 + 3] = v.w;
    }

    float h2acc = 0.0f;
    for (int j0 = 0; j0 < HID_DIM; j0 += 4) {
        float a0 = 0.f, a1 = 0.f, a2 = 0.f, a3 = 0.f;
#pragma unroll
        for (int k = 0; k < IN_DIM; k++) {
            float4 w = *reinterpret_cast<const float4*>(&sW1[k * HID_DIM + j0]);
            a0 = fmaf(yr[k], w.x, a0);
            a1 = fmaf(yr[k], w.y, a1);
            a2 = fmaf(yr[k], w.z, a2);
            a3 = fmaf(yr[k], w.w, a3);
        }
        float4 bb = *reinterpret_cast<const float4*>(&sB1[j0]);
        float4 w2 = *reinterpret_cast<const float4*>(&sW2[j0]);
        h2acc = fmaf(fmaxf(a0 + bb.x, 0.0f), w2.x, h2acc);
        h2acc = fmaf(fmaxf(a1 + bb.y, 0.0f), w2.y, h2acc);
        h2acc = fmaf(fmaxf(a2 + bb.z, 0.0f), w2.z, h2acc);
        h2acc = fmaf(fmaxf(a3 + bb.w, 0.0f), w2.w, h2acc);
    }

    g_h2[n] = h2acc;
    float dinv = g_dinv[n];
    out[n] = fmaf(h2acc, dinv * dinv, b2[0]);
}

__global__ void k_agg_h2(const int* __restrict__ src,
                         const int* __restrict__ dst,
                         float* __restrict__ out) {
    int e = blockIdx.x * blockDim.x + threadIdx.x;
    if (e >= N_EDGES) return;
    unsigned s = (unsigned)src[e];
    unsigned d = (unsigned)dst[e];
    if (s >= N_NODES || d >= N_NODES) return;
    float v = g_h2[s] * g_dinv[s] * g_dinv[d];
    atomicAdd(&out[d], v);
}

extern "C" void kernel_launch(void* const* d_in, const int* in_sizes, int n_in,
                              void* d_out, int out_size) {
    const float* x   = (const float*)d_in[0];
    const int*   ei  = (const int*)d_in[1];   // int32! (JAX x64 disabled)
    const float* W1  = (const float*)d_in[2];
    const float* b1  = (const float*)d_in[3];
    const float* W2  = (const float*)d_in[4];
    const float* b2  = (const float*)d_in[5];
    float* out       = (float*)d_out;

    const int* src = ei;
    const int* dst = ei + N_EDGES;

    const int T = 256;
    k_zero_deg<<<(N_NODES + T - 1) / T, T>>>();
    k_deg<<<(N_EDGES + T - 1) / T, T>>>(dst);
    k_dinv_init<<<(N_NODES * 16 + T - 1) / T, T>>>((const float4*)x);
    k_agg_x<<<(N_EDGES * 16 + T - 1) / T, T>>>((const float4*)x, src, dst);
    k_gemm_fused<<<(N_NODES + 255) / 256, 256>>>(W1, b1, W2, b2, out);
    k_agg_h2<<<(N_EDGES + T - 1) / T, T>>>(src, dst, out);
}

// round 4
// speedup vs baseline: 1.8171x; 1.8171x over previous
#include <cuda_runtime.h>

// LessonGCN on GB300: out = GCNConv(relu(GCNConv(x)))
// (A_norm @ x) @ W1 reordering; layer 2 (OUT_DIM=1) fused into GEMM epilogue.
// R4: atomic-free aggregation via per-call CSR build (count -> scan -> scatter),
//     then warp-per-node gather aggregation. edge_index is int32.

#define N_NODES 100000
#define N_EDGES 1600000
#define IN_DIM  64
#define HID_DIM 128
#define SCAN_B  1024
#define NB_SCAN ((N_NODES + SCAN_B - 1) / SCAN_B)   // 98

__device__ int   g_cnt[N_NODES];
__device__ int   g_off[N_NODES];
__device__ int   g_pos[N_NODES];
__device__ int   g_part[NB_SCAN];
__device__ int   g_csr_src[N_EDGES];
__device__ float g_dinv[N_NODES];
__device__ __align__(16) float g_y[(size_t)N_NODES * IN_DIM];
__device__ float g_h2[N_NODES];

__global__ void k_zero_cnt() {
    int i = blockIdx.x * blockDim.x + threadIdx.x;
    if (i < N_NODES) g_cnt[i] = 0;
}

__global__ void k_count(const int* __restrict__ dst) {
    int e = blockIdx.x * blockDim.x + threadIdx.x;
    if (e >= N_EDGES) return;
    unsigned d = (unsigned)dst[e];
    if (d < N_NODES) atomicAdd(&g_cnt[d], 1);
}

// Block-level exclusive scan of g_cnt -> g_off (local), totals -> g_part.
__global__ __launch_bounds__(SCAN_B) void k_scan1() {
    __shared__ int s[SCAN_B];
    int t = threadIdx.x;
    int idx = blockIdx.x * SCAN_B + t;
    int c = (idx < N_NODES) ? g_cnt[idx] : 0;
    s[t] = c;
    __syncthreads();
#pragma unroll
    for (int d = 1; d < SCAN_B; d <<= 1) {
        int v = (t >= d) ? s[t - d] : 0;
        __syncthreads();
        s[t] += v;
        __syncthreads();
    }
    if (idx < N_NODES) g_off[idx] = s[t] - c;  // exclusive
    if (t == SCAN_B - 1) g_part[blockIdx.x] = s[t];
}

// Exclusive scan of the 98 block totals (single block).
__global__ void k_scan2() {
    __shared__ int s[128];
    int t = threadIdx.x;
    int c = (t < NB_SCAN) ? g_part[t] : 0;
    s[t] = c;
    __syncthreads();
#pragma unroll
    for (int d = 1; d < 128; d <<= 1) {
        int v = (t >= d) ? s[t - d] : 0;
        __syncthreads();
        s[t] += v;
        __syncthreads();
    }
    if (t < NB_SCAN) g_part[t] = s[t] - c;
}

// Add block offsets, seed scatter cursors, compute dinv.
__global__ void k_scan3() {
    int i = blockIdx.x * blockDim.x + threadIdx.x;
    if (i >= N_NODES) return;
    int o = g_off[i] + g_part[i / SCAN_B];
    g_off[i] = o;
    g_pos[i] = o;
    g_dinv[i] = rsqrtf((float)g_cnt[i] + 1.0f);
}

__global__ void k_scatter(const int* __restrict__ src,
                          const int* __restrict__ dst) {
    int e = blockIdx.x * blockDim.x + threadIdx.x;
    if (e >= N_EDGES) return;
    unsigned s = (unsigned)src[e];
    unsigned d = (unsigned)dst[e];
    if (s >= N_NODES || d >= N_NODES) return;
    int p = atomicAdd(&g_pos[d], 1);
    g_csr_src[p] = (int)s;
}

// Warp per node: gather-aggregate incoming x rows (float2/lane = 64 floats/warp),
// add self-loop term, write y once. Zero atomics.
__global__ __launch_bounds__(256) void k_agg_x(const float2* __restrict__ x2) {
    int w = (blockIdx.x * blockDim.x + threadIdx.x) >> 5;
    int lane = threadIdx.x & 31;
    if (w >= N_NODES) return;
    int n = w;
    int base = g_off[n];
    int cnt = g_cnt[n];
    float dn = g_dinv[n];

    float2 a0 = make_float2(0.f, 0.f);
    float2 a1 = make_float2(0.f, 0.f);
    int j = 0;
    for (; j + 2 <= cnt; j += 2) {
        int s0 = g_csr_src[base + j];
        int s1 = g_csr_src[base + j + 1];
        float n0 = g_dinv[s0] * dn;
        float n1 = g_dinv[s1] * dn;
        float2 v0 = x2[(size_t)s0 * 32 + lane];
        float2 v1 = x2[(size_t)s1 * 32 + lane];
        a0.x = fmaf(v0.x, n0, a0.x); a0.y = fmaf(v0.y, n0, a0.y);
        a1.x = fmaf(v1.x, n1, a1.x); a1.y = fmaf(v1.y, n1, a1.y);
    }
    if (j < cnt) {
        int s0 = g_csr_src[base + j];
        float n0 = g_dinv[s0] * dn;
        float2 v0 = x2[(size_t)s0 * 32 + lane];
        a0.x = fmaf(v0.x, n0, a0.x); a0.y = fmaf(v0.y, n0, a0.y);
    }
    // self-loop: x[n] * dinv^2
    float sl = dn * dn;
    float2 vs = x2[(size_t)n * 32 + lane];
    a0.x = fmaf(vs.x, sl, a0.x + a1.x);
    a0.y = fmaf(vs.y, sl, a0.y + a1.y);
    reinterpret_cast<float2*>(g_y)[(size_t)n * 32 + lane] = a0;
}

// Fused GEMM: h2[n] = relu(y_n @ W1 + b1) . W2 ; out[n] = h2[n]*dinv^2 + b2[0]
__global__ __launch_bounds__(256) void k_gemm_fused(
    const float* __restrict__ W1, const float* __restrict__ b1,
    const float* __restrict__ W2, const float* __restrict__ b2,
    float* __restrict__ out) {
    __shared__ __align__(16) float sW1[IN_DIM * HID_DIM];
    __shared__ __align__(16) float sB1[HID_DIM];
    __shared__ __align__(16) float sW2[HID_DIM];

    for (int i = threadIdx.x; i < IN_DIM * HID_DIM; i += 256) sW1[i] = W1[i];
    if (threadIdx.x < HID_DIM) {
        sB1[threadIdx.x] = b1[threadIdx.x];
        sW2[threadIdx.x] = W2[threadIdx.x];
    }
    __syncthreads();

    int n = blockIdx.x * 256 + threadIdx.x;
    if (n >= N_NODES) return;

    float yr[IN_DIM];
    const float4* yp = reinterpret_cast<const float4*>(g_y + (size_t)n * IN_DIM);
#pragma unroll
    for (int k4 = 0; k4 < IN_DIM / 4; k4++) {
        float4 v = yp[k4];
        yr[4 * k4 + 0] = v.x;
        yr[4 * k4 + 1] = v.y;
        yr[4 * k4 + 2] = v.z;
        yr[4 * k4 + 3] = v.w;
    }

    float h2acc = 0.0f;
    for (int j0 = 0; j0 < HID_DIM; j0 += 4) {
        float a0 = 0.f, a1 = 0.f, a2 = 0.f, a3 = 0.f;
#pragma unroll
        for (int k = 0; k < IN_DIM; k++) {
            float4 w = *reinterpret_cast<const float4*>(&sW1[k * HID_DIM + j0]);
            a0 = fmaf(yr[k], w.x, a0);
            a1 = fmaf(yr[k], w.y, a1);
            a2 = fmaf(yr[k], w.z, a2);
            a3 = fmaf(yr[k], w.w, a3);
        }
        float4 bb = *reinterpret_cast<const float4*>(&sB1[j0]);
        float4 w2 = *reinterpret_cast<const float4*>(&sW2[j0]);
        h2acc = fmaf(fmaxf(a0 + bb.x, 0.0f), w2.x, h2acc);
        h2acc = fmaf(fmaxf(a1 + bb.y, 0.0f), w2.y, h2acc);
        h2acc = fmaf(fmaxf(a2 + bb.z, 0.0f), w2.z, h2acc);
        h2acc = fmaf(fmaxf(a3 + bb.w, 0.0f), w2.w, h2acc);
    }

    g_h2[n] = h2acc;
    float dinv = g_dinv[n];
    out[n] = fmaf(h2acc, dinv * dinv, b2[0]);
}

// Warp per node: gather h2[src]*dinv[src], warp-reduce, lane0 accumulates into out.
__global__ __launch_bounds__(256) void k_agg_h2(float* __restrict__ out) {
    int w = (blockIdx.x * blockDim.x + threadIdx.x) >> 5;
    int lane = threadIdx.x & 31;
    if (w >= N_NODES) return;
    int n = w;
    int base = g_off[n];
    int cnt = g_cnt[n];

    float acc = 0.0f;
    for (int j = lane; j < cnt; j += 32) {
        int s = g_csr_src[base + j];
        acc += g_h2[s] * g_dinv[s];
    }
#pragma unroll
    for (int o = 16; o > 0; o >>= 1)
        acc += __shfl_down_sync(0xFFFFFFFFu, acc, o);
    if (lane == 0 && acc != 0.0f)
        out[n] += acc * g_dinv[n];
    else if (lane == 0 && cnt > 0)
        out[n] += acc * g_dinv[n];  // (kept simple: unconditional path below)
}

extern "C" void kernel_launch(void* const* d_in, const int* in_sizes, int n_in,
                              void* d_out, int out_size) {
    const float* x   = (const float*)d_in[0];
    const int*   ei  = (const int*)d_in[1];   // int32 (JAX x64 disabled)
    const float* W1  = (const float*)d_in[2];
    const float* b1  = (const float*)d_in[3];
    const float* W2  = (const float*)d_in[4];
    const float* b2  = (const float*)d_in[5];
    float* out       = (float*)d_out;

    const int* src = ei;
    const int* dst = ei + N_EDGES;

    const int T = 256;
    k_zero_cnt<<<(N_NODES + T - 1) / T, T>>>();
    k_count<<<(N_EDGES + T - 1) / T, T>>>(dst);
    k_scan1<<<NB_SCAN, SCAN_B>>>();
    k_scan2<<<1, 128>>>();
    k_scan3<<<(N_NODES + T - 1) / T, T>>>();
    k_scatter<<<(N_EDGES + T - 1) / T, T>>>(src, dst);
    k_agg_x<<<(N_NODES * 32 + T - 1) / T, T>>>((const float2*)x);
    k_gemm_fused<<<(N_NODES + 255) / 256, 256>>>(W1, b1, W2, b2, out);
    k_agg_h2<<<(N_NODES * 32 + T - 1) / T, T>>>(out);
}

// round 5
// speedup vs baseline: 1.8480x; 1.0170x over previous
#include <cuda_runtime.h>

// LessonGCN on GB300: out = GCNConv(relu(GCNConv(x)))
// (A_norm @ x) @ W1 reordering; layer 2 (OUT_DIM=1) fused into GEMM epilogue.
// R5: packed fma.rn.f32x2 GEMM (2x fp32 path), scan2 folded into scan_fin,
//     g_pos removed (scatter bumps g_off, consumers use off - cnt).

#define N_NODES 100000
#define N_EDGES 1600000
#define IN_DIM  64
#define HID_DIM 128
#define SCAN_B  1024
#define NB_SCAN ((N_NODES + SCAN_B - 1) / SCAN_B)   // 98

__device__ int   g_cnt[N_NODES];
__device__ int   g_off[N_NODES];
__device__ int   g_part[NB_SCAN];
__device__ int   g_csr_src[N_EDGES];
__device__ float g_dinv[N_NODES];
__device__ __align__(16) float g_y[(size_t)N_NODES * IN_DIM];
__device__ float g_h2[N_NODES];

__global__ void k_zero_cnt() {
    int i = blockIdx.x * blockDim.x + threadIdx.x;
    if (i < N_NODES) g_cnt[i] = 0;
}

__global__ void k_count(const int* __restrict__ dst) {
    int e = blockIdx.x * blockDim.x + threadIdx.x;
    if (e >= N_EDGES) return;
    unsigned d = (unsigned)dst[e];
    if (d < N_NODES) atomicAdd(&g_cnt[d], 1);
}

// Block-level exclusive scan of g_cnt -> g_off (block-local), totals -> g_part.
__global__ __launch_bounds__(SCAN_B) void k_scan1() {
    __shared__ int s[SCAN_B];
    int t = threadIdx.x;
    int idx = blockIdx.x * SCAN_B + t;
    int c = (idx < N_NODES) ? g_cnt[idx] : 0;
    s[t] = c;
    __syncthreads();
#pragma unroll
    for (int d = 1; d < SCAN_B; d <<= 1) {
        int v = (t >= d) ? s[t - d] : 0;
        __syncthreads();
        s[t] += v;
        __syncthreads();
    }
    if (idx < N_NODES) g_off[idx] = s[t] - c;  // exclusive within block
    if (t == SCAN_B - 1) g_part[blockIdx.x] = s[t];
}

// Finalize: every block redundantly scans the 98 partials in smem (cheap),
// adds the global offset, computes dinv. No separate scan2 launch.
__global__ __launch_bounds__(256) void k_scan_fin() {
    __shared__ int sp[128];
    int t = threadIdx.x;
    if (t < 128) {
        int c = (t < NB_SCAN) ? g_part[t] : 0;
        sp[t] = c;
    }
    __syncthreads();
#pragma unroll
    for (int d = 1; d < 128; d <<= 1) {
        int v = 0;
        if (t < 128 && t >= d) v = sp[t - d];
        __syncthreads();
        if (t < 128) sp[t] += v;
        __syncthreads();
    }
    int i = blockIdx.x * blockDim.x + t;
    if (i >= N_NODES) return;
    int blk = i / SCAN_B;
    int excl = (blk == 0) ? 0 : sp[blk - 1];
    g_off[i] += excl;
    g_dinv[i] = rsqrtf((float)g_cnt[i] + 1.0f);
}

// Scatter src ids into CSR; g_off[d] advances to segment end (= off + cnt).
__global__ void k_scatter(const int* __restrict__ src,
                          const int* __restrict__ dst) {
    int e = blockIdx.x * blockDim.x + threadIdx.x;
    if (e >= N_EDGES) return;
    unsigned s = (unsigned)src[e];
    unsigned d = (unsigned)dst[e];
    if (s >= N_NODES || d >= N_NODES) return;
    int p = atomicAdd(&g_off[d], 1);
    g_csr_src[p] = (int)s;
}

// Warp per node: gather-aggregate incoming x rows (float2/lane = 64 floats/warp),
// add self-loop term, write y once. Zero atomics.
__global__ __launch_bounds__(256) void k_agg_x(const float2* __restrict__ x2) {
    int w = (blockIdx.x * blockDim.x + threadIdx.x) >> 5;
    int lane = threadIdx.x & 31;
    if (w >= N_NODES) return;
    int n = w;
    int cnt = g_cnt[n];
    int base = g_off[n] - cnt;  // off was advanced to end by scatter
    float dn = g_dinv[n];

    float2 a0 = make_float2(0.f, 0.f);
    float2 a1 = make_float2(0.f, 0.f);
    int j = 0;
    for (; j + 2 <= cnt; j += 2) {
        int s0 = g_csr_src[base + j];
        int s1 = g_csr_src[base + j + 1];
        float n0 = g_dinv[s0] * dn;
        float n1 = g_dinv[s1] * dn;
        float2 v0 = x2[(size_t)s0 * 32 + lane];
        float2 v1 = x2[(size_t)s1 * 32 + lane];
        a0.x = fmaf(v0.x, n0, a0.x); a0.y = fmaf(v0.y, n0, a0.y);
        a1.x = fmaf(v1.x, n1, a1.x); a1.y = fmaf(v1.y, n1, a1.y);
    }
    if (j < cnt) {
        int s0 = g_csr_src[base + j];
        float n0 = g_dinv[s0] * dn;
        float2 v0 = x2[(size_t)s0 * 32 + lane];
        a0.x = fmaf(v0.x, n0, a0.x); a0.y = fmaf(v0.y, n0, a0.y);
    }
    float sl = dn * dn;  // self-loop: x[n] * dinv^2
    float2 vs = x2[(size_t)n * 32 + lane];
    a0.x = fmaf(vs.x, sl, a0.x + a1.x);
    a0.y = fmaf(vs.y, sl, a0.y + a1.y);
    reinterpret_cast<float2*>(g_y)[(size_t)n * 32 + lane] = a0;
}

// Fused GEMM with packed f32x2 FMA: h2[n] = relu(y_n @ W1 + b1) . W2
// out[n] = h2[n]*dinv^2 + b2[0]. Output pairs (j, j+1) packed in b64 accumulators;
// W1 rows read from smem as ulonglong2 (LDS.128 -> two b64 regs, no re-pack).
__global__ __launch_bounds__(256) void k_gemm_fused(
    const float* __restrict__ W1, const float* __restrict__ b1,
    const float* __restrict__ W2, const float* __restrict__ b2,
    float* __restrict__ out) {
    __shared__ __align__(16) float sW1[IN_DIM * HID_DIM];
    __shared__ __align__(16) float sB1[HID_DIM];
    __shared__ __align__(16) float sW2[HID_DIM];

    for (int i = threadIdx.x; i < IN_DIM * HID_DIM; i += 256) sW1[i] = W1[i];
    if (threadIdx.x < HID_DIM) {
        sB1[threadIdx.x] = b1[threadIdx.x];
        sW2[threadIdx.x] = W2[threadIdx.x];
    }
    __syncthreads();

    int n = blockIdx.x * 256 + threadIdx.x;
    if (n >= N_NODES) return;

    float yr[IN_DIM];
    const float4* yp = reinterpret_cast<const float4*>(g_y + (size_t)n * IN_DIM);
#pragma unroll
    for (int k4 = 0; k4 < IN_DIM / 4; k4++) {
        float4 v = yp[k4];
        yr[4 * k4 + 0] = v.x;
        yr[4 * k4 + 1] = v.y;
        yr[4 * k4 + 2] = v.z;
        yr[4 * k4 + 3] = v.w;
    }

    float h2acc = 0.0f;
    for (int j0 = 0; j0 < HID_DIM; j0 += 32) {   // 4 passes, 16 packed accs each
        unsigned long long acc[16];
#pragma unroll
        for (int q = 0; q < 16; q++) acc[q] = 0ull;
#pragma unroll
        for (int k = 0; k < IN_DIM; k++) {
            unsigned long long yd;
            asm("mov.b64 %0, {%1, %1};" : "=l"(yd) : "f"(yr[k]));
            const ulonglong2* wrow =
                reinterpret_cast<const ulonglong2*>(&sW1[k * HID_DIM + j0]);
#pragma unroll
            for (int q = 0; q < 8; q++) {
                ulonglong2 w = wrow[q];
                asm("fma.rn.f32x2 %0, %1, %2, %0;" : "+l"(acc[2 * q]) : "l"(yd), "l"(w.x));
                asm("fma.rn.f32x2 %0, %1, %2, %0;" : "+l"(acc[2 * q + 1]) : "l"(yd), "l"(w.y));
            }
        }
#pragma unroll
        for (int q = 0; q < 16; q++) {
            float lo, hi;
            asm("mov.b64 {%0, %1}, %2;" : "=f"(lo), "=f"(hi) : "l"(acc[q]));
            int j = j0 + 2 * q;
            h2acc = fmaf(fmaxf(lo + sB1[j], 0.0f), sW2[j], h2acc);
            h2acc = fmaf(fmaxf(hi + sB1[j + 1], 0.0f), sW2[j + 1], h2acc);
        }
    }

    g_h2[n] = h2acc;
    float dinv = g_dinv[n];
    out[n] = fmaf(h2acc, dinv * dinv, b2[0]);
}

// Warp per node: gather h2[src]*dinv[src], warp-reduce, lane0 accumulates into out.
__global__ __launch_bounds__(256) void k_agg_h2(float* __restrict__ out) {
    int w = (blockIdx.x * blockDim.x + threadIdx.x) >> 5;
    int lane = threadIdx.x & 31;
    if (w >= N_NODES) return;
    int n = w;
    int cnt = g_cnt[n];
    int base = g_off[n] - cnt;

    float acc = 0.0f;
    for (int j = lane; j < cnt; j += 32) {
        int s = g_csr_src[base + j];
        acc += g_h2[s] * g_dinv[s];
    }
#pragma unroll
    for (int o = 16; o > 0; o >>= 1)
        acc += __shfl_down_sync(0xFFFFFFFFu, acc, o);
    if (lane == 0)
        out[n] += acc * g_dinv[n];
}

extern "C" void kernel_launch(void* const* d_in, const int* in_sizes, int n_in,
                              void* d_out, int out_size) {
    const float* x   = (const float*)d_in[0];
    const int*   ei  = (const int*)d_in[1];   // int32 (JAX x64 disabled)
    const float* W1  = (const float*)d_in[2];
    const float* b1  = (const float*)d_in[3];
    const float* W2  = (const float*)d_in[4];
    const float* b2  = (const float*)d_in[5];
    float* out       = (float*)d_out;

    const int* src = ei;
    const int* dst = ei + N_EDGES;

    const int T = 256;
    k_zero_cnt<<<(N_NODES + T - 1) / T, T>>>();
    k_count<<<(N_EDGES + T - 1) / T, T>>>(dst);
    k_scan1<<<NB_SCAN, SCAN_B>>>();
    k_scan_fin<<<(N_NODES + T - 1) / T, T>>>();
    k_scatter<<<(N_EDGES + T - 1) / T, T>>>(src, dst);
    k_agg_x<<<(N_NODES * 32 + T - 1) / T, T>>>((const float2*)x);
    k_gemm_fused<<<(N_NODES + 255) / 256, 256>>>(W1, b1, W2, b2, out);
    k_agg_h2<<<(N_NODES * 32 + T - 1) / T, T>>>(out);
}